// round 15
// baseline (speedup 1.0000x reference)
#include <cuda_runtime.h>
#include <cstdint>

// ---------------------------------------------------------------------------
// Round 14: ALU diet via metadata tables.
//   - kmeta[k>>2] (smem, uint16 slot<<10|f): whole gather decode = 1 LDS16.
//     One decode serves all 4 points of a thread (same k column).
//   - basep[point][29]: absolute table pointers incl. zero-page pad slot ->
//     branchless gather: LDS64 + LEA + LDG.128.
//   - B fragments: running pointer += 2048/chunk, immediate offsets.
//   - ldmatrix/STS: precomputed byte bases + (ch&1)*16896 ping-pong.
//   - smem overlays (pidx, Rbuf alias As) to stay under 48 KB static.
//   - mark_live folded into wf_precompute (g_live monotone, idempotent).
// ---------------------------------------------------------------------------

#define MPTS   32
#define TPB    256
#define KC     128
#define KPAD   9600
#define NCH    (KPAD / KC)   // 75
#define SA     132           // A smem row stride (u32)
#define RS     72            // reduce buffer row stride (floats)
#define NK8    (KPAD / 8)    // 1200
#define NCOMBO 960
#define NPTS   8192
#define STK    2720
#define WF4_N  (NK8 * 4 * 32)
#define WST_N  (STK * 16)

#define AS_BYTES   33792     // 2 * 32 * 132 * 4
#define BUF_BYTES  16896
#define KM_OFF     33792     // uint16[2432] = 4864
#define BP_OFF     38656     // ull[32*29]   = 7424
#define KEY_OFF    46080     // int[32]
#define SS_OFF     46208     // float[32]
#define SMEM_BYTES 46336

__device__ uint4 g_Wf4[NK8 * 4 * 32];
__device__ float g_Wst[STK * 64];
__device__ float g_Hst[NCOMBO * 64];
__device__ float g_SSst[NCOMBO];
__device__ int   g_live[NCOMBO];          // bss zero-init; monotone 0->1
__device__ alignas(16) float g_zero[4] = {0.f, 0.f, 0.f, 0.f};

__constant__ int c_OFF7[7][3] = {
    {0,0,0},{1,0,0},{-1,0,0},{0,1,0},{0,-1,0},{0,0,1},{0,0,-1}};
__constant__ int c_S14[14][3] = {
    {1,0,0},{-1,0,0},{0,1,0},{0,-1,0},{0,0,1},{0,0,-1},
    {1,1,1},{-1,-1,-1},{1,-1,-1},{-1,1,1},{1,1,-1},{-1,-1,1},{1,-1,1},{-1,1,-1}};
__constant__ int c_CORNER[8][3] = {
    {1,1,1},{-1,-1,-1},{1,-1,-1},{-1,1,1},{1,1,-1},{-1,-1,1},{1,-1,1},{-1,1,-1}};
__constant__ int c_ETEMP[11] = {-64,-8,-4,-2,-1,0,1,2,4,8,64};

__device__ __forceinline__ uint32_t f2tf32(float x) {
    uint32_t u;
    asm("cvt.rna.tf32.f32 %0, %1;" : "=r"(u) : "f"(x));
    return u;
}

__device__ __forceinline__ uint32_t s2u(const void* p) {
    uint32_t a;
    asm("{ .reg .u64 t; cvta.to.shared.u64 t, %1; cvt.u32.u64 %0, t; }"
        : "=r"(a) : "l"(p));
    return a;
}

__device__ __forceinline__ void mma8(float* c,
                                     uint32_t a0, uint32_t a1, uint32_t a2, uint32_t a3,
                                     uint32_t b0, uint32_t b1) {
    asm("mma.sync.aligned.m16n8k8.row.col.f32.tf32.tf32.f32 "
        "{%0,%1,%2,%3}, {%4,%5,%6,%7}, {%8,%9}, {%0,%1,%2,%3};"
        : "+f"(c[0]), "+f"(c[1]), "+f"(c[2]), "+f"(c[3])
        : "r"(a0), "r"(a1), "r"(a2), "r"(a3), "r"(b0), "r"(b1));
}

__device__ __forceinline__ float4 ld4p(unsigned long long base, int f) {
    const float* p = reinterpret_cast<const float*>((uintptr_t)base) + f;
    return *reinterpret_cast<const float4*>(p);
}

// ---------------------------------------------------------------------------
// Combined precompute: spatial B frags, ST B values, live-combo marking.
__global__ void __launch_bounds__(256)
wf_precompute_kernel(const float* __restrict__ w_down,
                     const float* __restrict__ rms_scale,
                     const float* __restrict__ d_t)
{
    int T = blockIdx.x * 256 + threadIdx.x;
    if (T < WF4_N) {
        int lane = T & 31;
        int nt2  = (T >> 5) & 3;
        int K8   = T >> 7;
        int ne = nt2 * 16 + (lane >> 2);
        int no = ne + 8;
        int k0 = K8 * 8 + (lane & 3);
        int k1 = k0 + 4;
        uint4 u;
        u.x = (k0 < 9520) ? f2tf32(w_down[k0 * 64 + ne] * rms_scale[k0]) : 0u;
        u.y = (k1 < 9520) ? f2tf32(w_down[k1 * 64 + ne] * rms_scale[k1]) : 0u;
        u.z = (k0 < 9520) ? f2tf32(w_down[k0 * 64 + no] * rms_scale[k0]) : 0u;
        u.w = (k1 < 9520) ? f2tf32(w_down[k1 * 64 + no] * rms_scale[k1]) : 0u;
        g_Wf4[T] = u;
    } else if (T < WF4_N + WST_N) {
        int idx = T - WF4_N;
        int kk  = idx >> 4;
        int n4  = (idx & 15) << 2;
        int k   = 9520 + kk;
        float s = rms_scale[k];
        float4 w = *reinterpret_cast<const float4*>(w_down + k * 64 + n4);
        float4 o;
        o.x = __uint_as_float(f2tf32(w.x * s));
        o.y = __uint_as_float(f2tf32(w.y * s));
        o.z = __uint_as_float(f2tf32(w.z * s));
        o.w = __uint_as_float(f2tf32(w.w * s));
        *reinterpret_cast<float4*>(g_Wst + kk * 64 + n4) = o;
    } else if (T < WF4_N + WST_N + NPTS) {
        float tv = d_t[T - WF4_N - WST_N];
        int key = ((int)(tv * 15.0f)) * 64 + (int)(tv * 63.0f);
        g_live[key] = 1;
    }
}

// ---------------------------------------------------------------------------
// ST combo precompute (gated) — unchanged from R13 (proven).
__global__ void __launch_bounds__(256)
st_precompute_kernel(const float* __restrict__ S1t,
                     const float* __restrict__ S2t,
                     const float* __restrict__ TF)
{
    __shared__ int   gbase[144];
    __shared__ float fst[STK];
    __shared__ float red[256];

    int c = blockIdx.x;
    if (!g_live[c]) return;
    int tb = c >> 6, tvv = c & 63;
    int tid = threadIdx.x;

    if (tid < 144) {
        int g = tid, b;
        if (g < 28) {
            int si = g >> 1; int tt = (g & 1) ? -1 : 1;
            int a  = (tb + c_S14[si][0] + 16) & 15;
            int bb = (tb + c_S14[si][1] + 16) & 15;
            int cc = (tb + c_S14[si][2] + 16) & 15;
            int dd = (tvv + tt + 64) & 63;
            b = (((((((a << 4) | bb) << 4) | cc) << 6) | dd) << 6);
        } else if (g < 56) {
            int gg = g - 28; int si = gg >> 1; int tt = (gg & 1) ? -1 : 1;
            int a  = (tb + c_S14[si][0] + 64) & 63;
            int bb = (tb + c_S14[si][1] + 64) & 63;
            int cc = (tb + c_S14[si][2] + 64) & 63;
            int dd = (tvv + tt + 64) & 63;
            b = (((((((a << 6) | bb) << 6) | cc) << 6) | dd) << 3);
        } else {
            int gg = g - 56; int ci = gg / 11, ti = gg - ci * 11;
            int a  = (tb + c_CORNER[ci][0] + 4) & 3;
            int bb = (tb + c_CORNER[ci][1] + 4) & 3;
            int cc = (tb + c_CORNER[ci][2] + 4) & 3;
            int dd = (tvv + c_ETEMP[ti] + 65536) & 65535;
            b = (((((((a << 2) | bb) << 2) | cc) << 16) | dd) << 3);
        }
        gbase[g] = b;
    }
    __syncthreads();

    float ssp = 0.f;
    for (int e4 = tid; e4 < STK / 4; e4 += 256) {
        int r = e4 << 2;
        const float* fp;
        if (r < 1792)      fp = S1t + gbase[r >> 6] + (r & 63);
        else if (r < 2016) { int rr = r - 1792; fp = S2t + gbase[28 + (rr >> 3)] + (rr & 7); }
        else               { int rr = r - 2016; fp = TF  + gbase[56 + (rr >> 3)] + (rr & 7); }
        float4 v = *reinterpret_cast<const float4*>(fp);
        v.x = fmaxf(v.x, 0.f); v.y = fmaxf(v.y, 0.f);
        v.z = fmaxf(v.z, 0.f); v.w = fmaxf(v.w, 0.f);
        ssp += v.x * v.x + v.y * v.y + v.z * v.z + v.w * v.w;
        fst[r + 0] = __uint_as_float(__float_as_uint(v.x) & 0xFFFFE000u);
        fst[r + 1] = __uint_as_float(__float_as_uint(v.y) & 0xFFFFE000u);
        fst[r + 2] = __uint_as_float(__float_as_uint(v.z) & 0xFFFFE000u);
        fst[r + 3] = __uint_as_float(__float_as_uint(v.w) & 0xFFFFE000u);
    }
    red[tid] = ssp;
    __syncthreads();
    for (int s = 128; s > 0; s >>= 1) {
        if (tid < s) red[tid] += red[tid + s];
        __syncthreads();
    }
    float ssT = red[0];
    __syncthreads();

    int n  = tid & 63;
    int sl = tid >> 6;
    int k0 = sl * (STK / 4);
    float acc = 0.f;
#pragma unroll 8
    for (int j = 0; j < STK / 4; j++) {
        acc += fst[k0 + j] * g_Wst[(k0 + j) * 64 + n];
    }
    red[tid] = acc;
    __syncthreads();
    if (sl == 0) {
        g_Hst[c * 64 + n] = red[n] + red[64 + n] + red[128 + n] + red[192 + n];
        if (n == 0) g_SSst[c] = ssT;
    }
}

// ---------------------------------------------------------------------------
__global__ void __launch_bounds__(TPB, 2)
stlt_fused_kernel(
    const float* __restrict__ d_pos, const float* __restrict__ d_dir,
    const float* __restrict__ d_t,
    const float* __restrict__ T0, const float* __restrict__ T1,
    const float* __restrict__ T2, const float* __restrict__ T3,
    const float* __restrict__ w_final, const float* __restrict__ b_final,
    float* __restrict__ d_out)
{
    __shared__ alignas(16) char smem_raw[SMEM_BYTES];

    uint32_t*           As      = reinterpret_cast<uint32_t*>(smem_raw);
    uint16_t*           kmeta   = reinterpret_cast<uint16_t*>(smem_raw + KM_OFF);
    unsigned long long* basep   = reinterpret_cast<unsigned long long*>(smem_raw + BP_OFF);
    int*                key_s   = reinterpret_cast<int*>(smem_raw + KEY_OFF);
    float*              sumsq_s = reinterpret_cast<float*>(smem_raw + SS_OFF);
    int*                pidx    = reinterpret_cast<int*>(smem_raw);      // overlay on As
    float*              Rbuf    = reinterpret_cast<float*>(smem_raw);    // overlay on As

    const int tid  = threadIdx.x;
    const int lane = tid & 31;
    const int warp = tid >> 5;
    const int kq   = warp >> 1;
    const int nh   = warp & 1;
    const int p0   = blockIdx.x * MPTS;

    if (tid < MPTS) {
        int gp = p0 + tid;
        float px = d_pos[gp * 3 + 0];
        float py = d_pos[gp * 3 + 1];
        float pz = d_pos[gp * 3 + 2];
        pidx[tid * 12 + 0]  = (int)(px * 127.0f);
        pidx[tid * 12 + 1]  = (int)(py * 127.0f);
        pidx[tid * 12 + 2]  = (int)(pz * 127.0f);
        pidx[tid * 12 + 3]  = (int)(px * 63.0f);
        pidx[tid * 12 + 4]  = (int)(py * 63.0f);
        pidx[tid * 12 + 5]  = (int)(pz * 63.0f);
        pidx[tid * 12 + 6]  = (int)(px * 31.0f);
        pidx[tid * 12 + 7]  = (int)(py * 31.0f);
        pidx[tid * 12 + 8]  = (int)(pz * 31.0f);
        pidx[tid * 12 + 9]  = (int)(px * 15.0f);
        pidx[tid * 12 + 10] = (int)(py * 15.0f);
        pidx[tid * 12 + 11] = (int)(pz * 15.0f);
        float tv = d_t[gp];
        key_s[tid] = ((int)(tv * 15.0f)) * 64 + (int)(tv * 63.0f);
    }
    __syncthreads();

    // ---- basep: absolute base pointers per (point, slot); slot 28 = zero --
    for (int e = tid; e < MPTS * 29; e += TPB) {
        int p = e / 29;
        int j = e - p * 29;
        unsigned long long ptr;
        if (j < 28) {
            int tau  = j / 7;
            int o    = j - tau * 7;
            int dlog = 7 - tau;
            int flog = 4 + 2 * tau;
            int d = 1 << dlog, m = d - 1;
            int cx = (pidx[p * 12 + tau * 3 + 0] + c_OFF7[o][0] + d) & m;
            int cy = (pidx[p * 12 + tau * 3 + 1] + c_OFF7[o][1] + d) & m;
            int cz = (pidx[p * 12 + tau * 3 + 2] + c_OFF7[o][2] + d) & m;
            int off = ((((cx << dlog) | cy) << dlog) | cz) << flog;
            const float* tb4 = (tau == 0) ? T0 : (tau == 1) ? T1 : (tau == 2) ? T2 : T3;
            ptr = (unsigned long long)(uintptr_t)(tb4 + off);
        } else {
            ptr = (unsigned long long)(uintptr_t)g_zero;
        }
        basep[e] = ptr;
    }
    // ---- kmeta: packed (slot<<10 | f) per k4 group; 2432 covers prefetch --
    for (int e = tid; e < 2432; e += TPB) {
        int k = e << 2;
        int slot, f;
        if (k < 112)       { slot = k >> 4;                   f = k & 15;   }
        else if (k < 560)  { int r = k - 112;  slot = 7  + (r >> 6);  f = r & 63;   }
        else if (k < 2352) { int r = k - 560;  slot = 14 + (r >> 8);  f = r & 255;  }
        else if (k < 9520) { int r = k - 2352; slot = 21 + (r >> 10); f = r & 1023; }
        else               { slot = 28; f = 0; }
        kmeta[e] = (uint16_t)((slot << 10) | f);
    }
    __syncthreads();

    float acc[2][4][4];
#pragma unroll
    for (int m = 0; m < 2; m++)
#pragma unroll
        for (int i = 0; i < 4; i++)
#pragma unroll
            for (int j = 0; j < 4; j++) acc[m][i][j] = 0.f;
    float ss[4] = {0.f, 0.f, 0.f, 0.f};

    const int lm_row = ((lane >> 3) & 1) * 8 + (lane & 7);
    const int lm_kof = (lane >> 4) * 4;
    const uint32_t As_a = s2u(smem_raw);

    // precomputed addresses
    int pb[4];
    int sts_off[4];
#pragma unroll
    for (int j = 0; j < 4; j++) {
        int p = (tid >> 5) + j * 8;
        pb[j] = p * 29;
        sts_off[j] = 4 * (p * SA + 4 * lane);
    }
    uint32_t lm_base0 = As_a + 4 * ((0 * 16 + lm_row) * SA + lm_kof) + kq * 128;
    uint32_t lm_base1 = As_a + 4 * ((1 * 16 + lm_row) * SA + lm_kof) + kq * 128;
    const uint4* Wch = g_Wf4 + ((kq * 4) << 7) + nh * 64 + lane;

    // ---- prologue gather (chunk 0) ----------------------------------------
    float4 v[4];
    {
        int meta = kmeta[lane];
        int slot = meta >> 10, f = meta & 1023;
#pragma unroll
        for (int j = 0; j < 4; j++) v[j] = ld4p(basep[pb[j] + slot], f);
    }

    int kmi = 32 + lane;   // kmeta index of chunk ch+1
    for (int ch = 0; ch < NCH; ch++) {
        const uint32_t bo = (ch & 1) ? (uint32_t)BUF_BYTES : 0u;

        // ---- STS: relu + sumsq + store raw fp32 ---------------------------
#pragma unroll
        for (int j = 0; j < 4; j++) {
            float4 w = v[j];
            w.x = fmaxf(w.x, 0.f); w.y = fmaxf(w.y, 0.f);
            w.z = fmaxf(w.z, 0.f); w.w = fmaxf(w.w, 0.f);
            ss[j] += w.x * w.x + w.y * w.y + w.z * w.z + w.w * w.w;
            *reinterpret_cast<float4*>(smem_raw + sts_off[j] + bo) = w;
        }
        __syncthreads();

        // ---- prefetch chunk ch+1 (branchless; pad reads hit g_zero) -------
        {
            int meta = kmeta[kmi];
            int slot = meta >> 10, f = meta & 1023;
#pragma unroll
            for (int j = 0; j < 4; j++) v[j] = ld4p(basep[pb[j] + slot], f);
        }
        kmi += 32;

        // ---- mma ----------------------------------------------------------
        uint32_t a0b = lm_base0 + bo;
        uint32_t a1b = lm_base1 + bo;
#pragma unroll
        for (int g = 0; g < 4; g++) {
            uint4 bq0 = Wch[g * 128];
            uint4 bq1 = Wch[g * 128 + 32];
            uint32_t a0, a1, a2, a3;
            asm volatile("ldmatrix.sync.aligned.m8n8.x4.shared.b16 {%0,%1,%2,%3}, [%4];"
                         : "=r"(a0), "=r"(a1), "=r"(a2), "=r"(a3) : "r"(a0b + g * 32));
            mma8(acc[0][0], a0, a1, a2, a3, bq0.x, bq0.y);
            mma8(acc[0][1], a0, a1, a2, a3, bq0.z, bq0.w);
            mma8(acc[0][2], a0, a1, a2, a3, bq1.x, bq1.y);
            mma8(acc[0][3], a0, a1, a2, a3, bq1.z, bq1.w);
            asm volatile("ldmatrix.sync.aligned.m8n8.x4.shared.b16 {%0,%1,%2,%3}, [%4];"
                         : "=r"(a0), "=r"(a1), "=r"(a2), "=r"(a3) : "r"(a1b + g * 32));
            mma8(acc[1][0], a0, a1, a2, a3, bq0.x, bq0.y);
            mma8(acc[1][1], a0, a1, a2, a3, bq0.z, bq0.w);
            mma8(acc[1][2], a0, a1, a2, a3, bq1.x, bq1.y);
            mma8(acc[1][3], a0, a1, a2, a3, bq1.z, bq1.w);
        }
        Wch += 2048;
    }
    __syncthreads();   // As dead; Rbuf overlay becomes safe

    // ---- sumsq: warp reduce + ST part -------------------------------------
#pragma unroll
    for (int s = 16; s >= 1; s >>= 1) {
#pragma unroll
        for (int j = 0; j < 4; j++)
            ss[j] += __shfl_xor_sync(0xffffffffu, ss[j], s);
    }
    if (lane == 0) {
#pragma unroll
        for (int j = 0; j < 4; j++) {
            int p = warp + 8 * j;
            sumsq_s[p] = ss[j] + g_SSst[key_s[p]];
        }
    }

    // ---- cross-k acc reduction (serialized by kq) -------------------------
    {
        int row = lane >> 2;
        int cb  = nh * 32 + (lane & 3) * 2;
        if (kq == 3) {
#pragma unroll
            for (int mt = 0; mt < 2; mt++)
#pragma unroll
            for (int nt = 0; nt < 4; nt++) {
                int col = cb + nt * 8;
                int r0 = mt * 16 + row;
                Rbuf[r0 * RS + col]           = acc[mt][nt][0];
                Rbuf[r0 * RS + col + 1]       = acc[mt][nt][1];
                Rbuf[(r0 + 8) * RS + col]     = acc[mt][nt][2];
                Rbuf[(r0 + 8) * RS + col + 1] = acc[mt][nt][3];
            }
        }
        __syncthreads();
        if (kq == 2) {
#pragma unroll
            for (int mt = 0; mt < 2; mt++)
#pragma unroll
            for (int nt = 0; nt < 4; nt++) {
                int col = cb + nt * 8;
                int r0 = mt * 16 + row;
                Rbuf[r0 * RS + col]           += acc[mt][nt][0];
                Rbuf[r0 * RS + col + 1]       += acc[mt][nt][1];
                Rbuf[(r0 + 8) * RS + col]     += acc[mt][nt][2];
                Rbuf[(r0 + 8) * RS + col + 1] += acc[mt][nt][3];
            }
        }
        __syncthreads();
        if (kq == 1) {
#pragma unroll
            for (int mt = 0; mt < 2; mt++)
#pragma unroll
            for (int nt = 0; nt < 4; nt++) {
                int col = cb + nt * 8;
                int r0 = mt * 16 + row;
                Rbuf[r0 * RS + col]           += acc[mt][nt][0];
                Rbuf[r0 * RS + col + 1]       += acc[mt][nt][1];
                Rbuf[(r0 + 8) * RS + col]     += acc[mt][nt][2];
                Rbuf[(r0 + 8) * RS + col + 1] += acc[mt][nt][3];
            }
        }
        __syncthreads();
        if (kq == 0) {
#pragma unroll
            for (int mt = 0; mt < 2; mt++) {
                int r0 = mt * 16 + row;
                int r1 = r0 + 8;
                const float* H0 = g_Hst + key_s[r0] * 64;
                const float* H1 = g_Hst + key_s[r1] * 64;
                float inv0 = 1.0f / (sqrtf(sumsq_s[r0] * (1.0f / 12240.0f)) + 1e-8f);
                float inv1 = 1.0f / (sqrtf(sumsq_s[r1] * (1.0f / 12240.0f)) + 1e-8f);
#pragma unroll
                for (int nt = 0; nt < 4; nt++) {
                    int col = cb + nt * 8;
                    Rbuf[r0 * RS + col]     = fmaxf((acc[mt][nt][0] + Rbuf[r0 * RS + col]     + H0[col])     * inv0, 0.f);
                    Rbuf[r0 * RS + col + 1] = fmaxf((acc[mt][nt][1] + Rbuf[r0 * RS + col + 1] + H0[col + 1]) * inv0, 0.f);
                    Rbuf[r1 * RS + col]     = fmaxf((acc[mt][nt][2] + Rbuf[r1 * RS + col]     + H1[col])     * inv1, 0.f);
                    Rbuf[r1 * RS + col + 1] = fmaxf((acc[mt][nt][3] + Rbuf[r1 * RS + col + 1] + H1[col + 1]) * inv1, 0.f);
                }
            }
        }
    }
    __syncthreads();

    // ---- final tiny layer + sigmoid ---------------------------------------
    if (tid < MPTS) {
        int gp = p0 + tid;
        float o0 = b_final[0], o1 = b_final[1], o2 = b_final[2], o3 = b_final[3];
#pragma unroll 8
        for (int i = 0; i < 64; i++) {
            float h = Rbuf[tid * RS + i];
            float4 wf = *reinterpret_cast<const float4*>(w_final + i * 4);
            o0 += h * wf.x; o1 += h * wf.y; o2 += h * wf.z; o3 += h * wf.w;
        }
#pragma unroll
        for (int c = 0; c < 3; c++) {
            float dv = d_dir[gp * 3 + c];
            float4 wf = *reinterpret_cast<const float4*>(w_final + (64 + c) * 4);
            o0 += dv * wf.x; o1 += dv * wf.y; o2 += dv * wf.z; o3 += dv * wf.w;
        }
        {
            float tv = d_t[gp];
            float4 wf = *reinterpret_cast<const float4*>(w_final + 67 * 4);
            o0 += tv * wf.x; o1 += tv * wf.y; o2 += tv * wf.z; o3 += tv * wf.w;
        }
        d_out[gp * 4 + 0] = 1.0f / (1.0f + expf(-o0));
        d_out[gp * 4 + 1] = 1.0f / (1.0f + expf(-o1));
        d_out[gp * 4 + 2] = 1.0f / (1.0f + expf(-o2));
        d_out[gp * 4 + 3] = 1.0f / (1.0f + expf(-o3));
    }
}

extern "C" void kernel_launch(void* const* d_in, const int* in_sizes, int n_in,
                              void* d_out, int out_size) {
    const float* pos       = (const float*)d_in[0];
    const float* dirv      = (const float*)d_in[1];
    const float* t         = (const float*)d_in[2];
    const float* table0    = (const float*)d_in[3];
    const float* table1    = (const float*)d_in[4];
    const float* table2    = (const float*)d_in[5];
    const float* table3    = (const float*)d_in[6];
    const float* st1       = (const float*)d_in[7];
    const float* st2       = (const float*)d_in[8];
    const float* tf3       = (const float*)d_in[9];
    const float* rms_scale = (const float*)d_in[10];
    const float* w_down    = (const float*)d_in[11];
    const float* w_final   = (const float*)d_in[12];
    const float* b_final   = (const float*)d_in[13];
    float* out = (float*)d_out;

    wf_precompute_kernel<<<(WF4_N + WST_N + NPTS + 255) / 256, 256>>>(w_down, rms_scale, t);
    st_precompute_kernel<<<NCOMBO, 256>>>(st1, st2, tf3);
    stlt_fused_kernel<<<8192 / MPTS, TPB>>>(
        pos, dirv, t, table0, table1, table2, table3,
        w_final, b_final, out);
}

// round 16
// speedup vs baseline: 1.2329x; 1.2329x over previous
#include <cuda_runtime.h>
#include <cstdint>

// ---------------------------------------------------------------------------
// Round 15: revert main kernel to proven R13 form (R14's smem-metadata gather
//   added LDS latency to the critical path -> regression). Keep R14's helper
//   consolidation (mark_live folded into wf_precompute, 3 launches). One
//   contained delta in the mma phase: running B pointer (no size_t mul chain).
// ---------------------------------------------------------------------------

#define MPTS   32
#define TPB    256
#define KC     128
#define KPAD   9600          // spatial K only (9520 padded to 75*128)
#define NCH    (KPAD / KC)   // 75
#define SA     132           // A smem row stride (u32)
#define RS     72            // reduce buffer row stride (floats)
#define NK8    (KPAD / 8)    // 1200
#define NB     28            // spatial base-table entries per point
#define NCOMBO 960
#define NPTS   8192
#define STK    2720
#define WF4_N  (NK8 * 4 * 32)
#define WST_N  (STK * 16)

__device__ uint4 g_Wf4[NK8 * 4 * 32];
__device__ float g_Wst[STK * 64];
__device__ float g_Hst[NCOMBO * 64];
__device__ float g_SSst[NCOMBO];
__device__ int   g_live[NCOMBO];     // bss zero-init; monotone 0->1, idempotent

__constant__ int c_OFF7[7][3] = {
    {0,0,0},{1,0,0},{-1,0,0},{0,1,0},{0,-1,0},{0,0,1},{0,0,-1}};
__constant__ int c_S14[14][3] = {
    {1,0,0},{-1,0,0},{0,1,0},{0,-1,0},{0,0,1},{0,0,-1},
    {1,1,1},{-1,-1,-1},{1,-1,-1},{-1,1,1},{1,1,-1},{-1,-1,1},{1,-1,1},{-1,1,-1}};
__constant__ int c_CORNER[8][3] = {
    {1,1,1},{-1,-1,-1},{1,-1,-1},{-1,1,1},{1,1,-1},{-1,-1,1},{1,-1,1},{-1,1,-1}};
__constant__ int c_ETEMP[11] = {-64,-8,-4,-2,-1,0,1,2,4,8,64};

__device__ __forceinline__ uint32_t f2tf32(float x) {
    uint32_t u;
    asm("cvt.rna.tf32.f32 %0, %1;" : "=r"(u) : "f"(x));
    return u;
}

__device__ __forceinline__ uint32_t s2u(const void* p) {
    uint32_t a;
    asm("{ .reg .u64 t; cvta.to.shared.u64 t, %1; cvt.u32.u64 %0, t; }"
        : "=r"(a) : "l"(p));
    return a;
}

__device__ __forceinline__ void mma8(float* c,
                                     uint32_t a0, uint32_t a1, uint32_t a2, uint32_t a3,
                                     uint32_t b0, uint32_t b1) {
    asm("mma.sync.aligned.m16n8k8.row.col.f32.tf32.tf32.f32 "
        "{%0,%1,%2,%3}, {%4,%5,%6,%7}, {%8,%9}, {%0,%1,%2,%3};"
        : "+f"(c[0]), "+f"(c[1]), "+f"(c[2]), "+f"(c[3])
        : "r"(a0), "r"(a1), "r"(a2), "r"(a3), "r"(b0), "r"(b1));
}

// ---------------------------------------------------------------------------
// Combined precompute: spatial B frags, ST B values, live-combo marking.
__global__ void __launch_bounds__(256)
wf_precompute_kernel(const float* __restrict__ w_down,
                     const float* __restrict__ rms_scale,
                     const float* __restrict__ d_t)
{
    int T = blockIdx.x * 256 + threadIdx.x;
    if (T < WF4_N) {
        int lane = T & 31;
        int nt2  = (T >> 5) & 3;
        int K8   = T >> 7;
        int ne = nt2 * 16 + (lane >> 2);
        int no = ne + 8;
        int k0 = K8 * 8 + (lane & 3);
        int k1 = k0 + 4;
        uint4 u;
        u.x = (k0 < 9520) ? f2tf32(w_down[k0 * 64 + ne] * rms_scale[k0]) : 0u;
        u.y = (k1 < 9520) ? f2tf32(w_down[k1 * 64 + ne] * rms_scale[k1]) : 0u;
        u.z = (k0 < 9520) ? f2tf32(w_down[k0 * 64 + no] * rms_scale[k0]) : 0u;
        u.w = (k1 < 9520) ? f2tf32(w_down[k1 * 64 + no] * rms_scale[k1]) : 0u;
        g_Wf4[T] = u;
    } else if (T < WF4_N + WST_N) {
        int idx = T - WF4_N;
        int kk  = idx >> 4;
        int n4  = (idx & 15) << 2;
        int k   = 9520 + kk;
        float s = rms_scale[k];
        float4 w = *reinterpret_cast<const float4*>(w_down + k * 64 + n4);
        float4 o;
        o.x = __uint_as_float(f2tf32(w.x * s));
        o.y = __uint_as_float(f2tf32(w.y * s));
        o.z = __uint_as_float(f2tf32(w.z * s));
        o.w = __uint_as_float(f2tf32(w.w * s));
        *reinterpret_cast<float4*>(g_Wst + kk * 64 + n4) = o;
    } else if (T < WF4_N + WST_N + NPTS) {
        float tv = d_t[T - WF4_N - WST_N];
        int key = ((int)(tv * 15.0f)) * 64 + (int)(tv * 63.0f);
        g_live[key] = 1;
    }
}

// ---------------------------------------------------------------------------
// ST combo precompute (gated) — proven R13 version.
__global__ void __launch_bounds__(256)
st_precompute_kernel(const float* __restrict__ S1t,
                     const float* __restrict__ S2t,
                     const float* __restrict__ TF)
{
    __shared__ int   gbase[144];
    __shared__ float fst[STK];
    __shared__ float red[256];

    int c = blockIdx.x;
    if (!g_live[c]) return;
    int tb = c >> 6, tvv = c & 63;
    int tid = threadIdx.x;

    if (tid < 144) {
        int g = tid, b;
        if (g < 28) {
            int si = g >> 1; int tt = (g & 1) ? -1 : 1;
            int a  = (tb + c_S14[si][0] + 16) & 15;
            int bb = (tb + c_S14[si][1] + 16) & 15;
            int cc = (tb + c_S14[si][2] + 16) & 15;
            int dd = (tvv + tt + 64) & 63;
            b = (((((((a << 4) | bb) << 4) | cc) << 6) | dd) << 6);
        } else if (g < 56) {
            int gg = g - 28; int si = gg >> 1; int tt = (gg & 1) ? -1 : 1;
            int a  = (tb + c_S14[si][0] + 64) & 63;
            int bb = (tb + c_S14[si][1] + 64) & 63;
            int cc = (tb + c_S14[si][2] + 64) & 63;
            int dd = (tvv + tt + 64) & 63;
            b = (((((((a << 6) | bb) << 6) | cc) << 6) | dd) << 3);
        } else {
            int gg = g - 56; int ci = gg / 11, ti = gg - ci * 11;
            int a  = (tb + c_CORNER[ci][0] + 4) & 3;
            int bb = (tb + c_CORNER[ci][1] + 4) & 3;
            int cc = (tb + c_CORNER[ci][2] + 4) & 3;
            int dd = (tvv + c_ETEMP[ti] + 65536) & 65535;
            b = (((((((a << 2) | bb) << 2) | cc) << 16) | dd) << 3);
        }
        gbase[g] = b;
    }
    __syncthreads();

    float ssp = 0.f;
    for (int e4 = tid; e4 < STK / 4; e4 += 256) {
        int r = e4 << 2;
        const float* fp;
        if (r < 1792)      fp = S1t + gbase[r >> 6] + (r & 63);
        else if (r < 2016) { int rr = r - 1792; fp = S2t + gbase[28 + (rr >> 3)] + (rr & 7); }
        else               { int rr = r - 2016; fp = TF  + gbase[56 + (rr >> 3)] + (rr & 7); }
        float4 v = *reinterpret_cast<const float4*>(fp);
        v.x = fmaxf(v.x, 0.f); v.y = fmaxf(v.y, 0.f);
        v.z = fmaxf(v.z, 0.f); v.w = fmaxf(v.w, 0.f);
        ssp += v.x * v.x + v.y * v.y + v.z * v.z + v.w * v.w;
        fst[r + 0] = __uint_as_float(__float_as_uint(v.x) & 0xFFFFE000u);
        fst[r + 1] = __uint_as_float(__float_as_uint(v.y) & 0xFFFFE000u);
        fst[r + 2] = __uint_as_float(__float_as_uint(v.z) & 0xFFFFE000u);
        fst[r + 3] = __uint_as_float(__float_as_uint(v.w) & 0xFFFFE000u);
    }
    red[tid] = ssp;
    __syncthreads();
    for (int s = 128; s > 0; s >>= 1) {
        if (tid < s) red[tid] += red[tid + s];
        __syncthreads();
    }
    float ssT = red[0];
    __syncthreads();

    int n  = tid & 63;
    int sl = tid >> 6;
    int k0 = sl * (STK / 4);
    float acc = 0.f;
#pragma unroll 8
    for (int j = 0; j < STK / 4; j++) {
        acc += fst[k0 + j] * g_Wst[(k0 + j) * 64 + n];
    }
    red[tid] = acc;
    __syncthreads();
    if (sl == 0) {
        g_Hst[c * 64 + n] = red[n] + red[64 + n] + red[128 + n] + red[192 + n];
        if (n == 0) g_SSst[c] = ssT;
    }
}

// ---------------------------------------------------------------------------
// Gather 4 consecutive spatial features via precomputed per-point base table.
__device__ __forceinline__ float4 gather4b(
    int k, const int* __restrict__ bp,
    const float* __restrict__ T0, const float* __restrict__ T1,
    const float* __restrict__ T2, const float* __restrict__ T3)
{
    if (k < 9520) {
        const float* tab; int r, flog, bi;
        if (k < 112)       { tab = T0; r = k;        flog = 4;  bi = 0;  }
        else if (k < 560)  { tab = T1; r = k - 112;  flog = 6;  bi = 7;  }
        else if (k < 2352) { tab = T2; r = k - 560;  flog = 8;  bi = 14; }
        else               { tab = T3; r = k - 2352; flog = 10; bi = 21; }
        int o = r >> flog;
        int f = r & ((1 << flog) - 1);
        return *reinterpret_cast<const float4*>(tab + bp[bi + o] + f);
    }
    return make_float4(0.f, 0.f, 0.f, 0.f);   // pad [9520,9600)
}

// ---------------------------------------------------------------------------
__global__ void __launch_bounds__(TPB, 2)
stlt_fused_kernel(
    const float* __restrict__ d_pos, const float* __restrict__ d_dir,
    const float* __restrict__ d_t,
    const float* __restrict__ T0, const float* __restrict__ T1,
    const float* __restrict__ T2, const float* __restrict__ T3,
    const float* __restrict__ w_final, const float* __restrict__ b_final,
    float* __restrict__ d_out)
{
    __shared__ alignas(16) uint32_t As[2 * MPTS * SA];   // double-buffered A
    __shared__ alignas(16) float    Rbuf[MPTS * RS];
    __shared__ int      bases[MPTS * NB];
    __shared__ int      pidx[MPTS][12];
    __shared__ int      key_s[MPTS];
    __shared__ float    sumsq_s[MPTS];

    const int tid  = threadIdx.x;
    const int lane = tid & 31;
    const int warp = tid >> 5;
    const int kq   = warp >> 1;     // k-quarter 0..3
    const int nh   = warp & 1;      // n-half 0..1 (cols [nh*32, +32))
    const int p0   = blockIdx.x * MPTS;

    if (tid < MPTS) {
        int gp = p0 + tid;
        float px = d_pos[gp * 3 + 0];
        float py = d_pos[gp * 3 + 1];
        float pz = d_pos[gp * 3 + 2];
        pidx[tid][0]  = (int)(px * 127.0f);
        pidx[tid][1]  = (int)(py * 127.0f);
        pidx[tid][2]  = (int)(pz * 127.0f);
        pidx[tid][3]  = (int)(px * 63.0f);
        pidx[tid][4]  = (int)(py * 63.0f);
        pidx[tid][5]  = (int)(pz * 63.0f);
        pidx[tid][6]  = (int)(px * 31.0f);
        pidx[tid][7]  = (int)(py * 31.0f);
        pidx[tid][8]  = (int)(pz * 31.0f);
        pidx[tid][9]  = (int)(px * 15.0f);
        pidx[tid][10] = (int)(py * 15.0f);
        pidx[tid][11] = (int)(pz * 15.0f);
        float tv = d_t[gp];
        key_s[tid] = ((int)(tv * 15.0f)) * 64 + (int)(tv * 63.0f);
    }
    __syncthreads();

    // ---- fill per-point spatial base-address table -------------------------
    for (int e = tid; e < MPTS * NB; e += TPB) {
        int p = e / NB;
        int j = e - p * NB;
        int tau  = j / 7;
        int o    = j - tau * 7;
        int dlog = 7 - tau;
        int flog = 4 + 2 * tau;
        int d = 1 << dlog, m = d - 1;
        int cx = (pidx[p][tau * 3 + 0] + c_OFF7[o][0] + d) & m;
        int cy = (pidx[p][tau * 3 + 1] + c_OFF7[o][1] + d) & m;
        int cz = (pidx[p][tau * 3 + 2] + c_OFF7[o][2] + d) & m;
        bases[e] = ((((cx << dlog) | cy) << dlog) | cz) << flog;
    }
    __syncthreads();

    float acc[2][4][4];
#pragma unroll
    for (int m = 0; m < 2; m++)
#pragma unroll
        for (int i = 0; i < 4; i++)
#pragma unroll
            for (int j = 0; j < 4; j++) acc[m][i][j] = 0.f;
    float ss[4] = {0.f, 0.f, 0.f, 0.f};

    const int lm_row = ((lane >> 3) & 1) * 8 + (lane & 7);
    const int lm_kof = (lane >> 4) * 4;

    // running B-fragment pointer for this warp (delta per chunk = 16*128 uint4)
    const uint4* Wch = g_Wf4 + ((size_t)(kq * 4) << 7) + (2 * nh) * 32 + lane;

    // ---- prologue: gather chunk 0 into regs (4 float4 per thread) ---------
    float4 v[4];
#pragma unroll
    for (int j = 0; j < 4; j++) {
        int i  = tid + j * TPB;
        int p  = i >> 5;
        int k4 = (i & 31) << 2;
        v[j] = gather4b(k4, bases + p * NB, T0, T1, T2, T3);
    }

    for (int ch = 0; ch < NCH; ch++) {
        uint32_t* buf = As + (ch & 1) * (MPTS * SA);
        const int kb  = ch * KC;

        // ---- STS: relu + per-thread sumsq + store raw fp32 bits ----------
#pragma unroll
        for (int j = 0; j < 4; j++) {
            float4 w = v[j];
            w.x = fmaxf(w.x, 0.f); w.y = fmaxf(w.y, 0.f);
            w.z = fmaxf(w.z, 0.f); w.w = fmaxf(w.w, 0.f);
            ss[j] += w.x * w.x + w.y * w.y + w.z * w.z + w.w * w.w;
            int i = tid + j * TPB;
            *reinterpret_cast<float4*>(&buf[(i >> 5) * SA + ((i & 31) << 2)]) = w;
        }
        __syncthreads();

        // ---- prefetch next chunk (overlaps mma) ---------------------------
        if (ch + 1 < NCH) {
#pragma unroll
            for (int j = 0; j < 4; j++) {
                int i  = tid + j * TPB;
                int p  = i >> 5;
                int k4 = (i & 31) << 2;
                v[j] = gather4b(kb + KC + k4, bases + p * NB, T0, T1, T2, T3);
            }
        }

        // ---- mma: warp covers k8 in [kq*4, +4), n [nh*32, +32), m all 32 --
#pragma unroll
        for (int g = 0; g < 4; g++) {
            int kk = (kq * 4 + g) * 8;
            uint4 bq0 = Wch[g * 128];
            uint4 bq1 = Wch[g * 128 + 32];
#pragma unroll
            for (int mt = 0; mt < 2; mt++) {
                uint32_t a0, a1, a2, a3;
                uint32_t addr = s2u(&buf[(mt * 16 + lm_row) * SA + kk + lm_kof]);
                asm volatile("ldmatrix.sync.aligned.m8n8.x4.shared.b16 {%0,%1,%2,%3}, [%4];"
                             : "=r"(a0), "=r"(a1), "=r"(a2), "=r"(a3) : "r"(addr));
                mma8(acc[mt][0], a0, a1, a2, a3, bq0.x, bq0.y);
                mma8(acc[mt][1], a0, a1, a2, a3, bq0.z, bq0.w);
                mma8(acc[mt][2], a0, a1, a2, a3, bq1.x, bq1.y);
                mma8(acc[mt][3], a0, a1, a2, a3, bq1.z, bq1.w);
            }
        }
        Wch += 2048;
    }

    // ---- sumsq: warp reduce + ST combo part, single writer ----------------
#pragma unroll
    for (int s = 16; s >= 1; s >>= 1) {
#pragma unroll
        for (int j = 0; j < 4; j++)
            ss[j] += __shfl_xor_sync(0xffffffffu, ss[j], s);
    }
    if (lane == 0) {
#pragma unroll
        for (int j = 0; j < 4; j++) {
            int p = warp + 8 * j;
            sumsq_s[p] = ss[j] + g_SSst[key_s[p]];
        }
    }

    // ---- cross-k acc reduction (serialized by kq; both nh in parallel) ----
    {
        int row = lane >> 2;
        int cb  = nh * 32 + (lane & 3) * 2;
        if (kq == 3) {
#pragma unroll
            for (int mt = 0; mt < 2; mt++)
#pragma unroll
            for (int nt = 0; nt < 4; nt++) {
                int col = cb + nt * 8;
                int r0 = mt * 16 + row;
                Rbuf[r0 * RS + col]           = acc[mt][nt][0];
                Rbuf[r0 * RS + col + 1]       = acc[mt][nt][1];
                Rbuf[(r0 + 8) * RS + col]     = acc[mt][nt][2];
                Rbuf[(r0 + 8) * RS + col + 1] = acc[mt][nt][3];
            }
        }
        __syncthreads();
        if (kq == 2) {
#pragma unroll
            for (int mt = 0; mt < 2; mt++)
#pragma unroll
            for (int nt = 0; nt < 4; nt++) {
                int col = cb + nt * 8;
                int r0 = mt * 16 + row;
                Rbuf[r0 * RS + col]           += acc[mt][nt][0];
                Rbuf[r0 * RS + col + 1]       += acc[mt][nt][1];
                Rbuf[(r0 + 8) * RS + col]     += acc[mt][nt][2];
                Rbuf[(r0 + 8) * RS + col + 1] += acc[mt][nt][3];
            }
        }
        __syncthreads();
        if (kq == 1) {
#pragma unroll
            for (int mt = 0; mt < 2; mt++)
#pragma unroll
            for (int nt = 0; nt < 4; nt++) {
                int col = cb + nt * 8;
                int r0 = mt * 16 + row;
                Rbuf[r0 * RS + col]           += acc[mt][nt][0];
                Rbuf[r0 * RS + col + 1]       += acc[mt][nt][1];
                Rbuf[(r0 + 8) * RS + col]     += acc[mt][nt][2];
                Rbuf[(r0 + 8) * RS + col + 1] += acc[mt][nt][3];
            }
        }
        __syncthreads();
        if (kq == 0) {
#pragma unroll
            for (int mt = 0; mt < 2; mt++) {
                int r0 = mt * 16 + row;
                int r1 = r0 + 8;
                const float* H0 = g_Hst + key_s[r0] * 64;
                const float* H1 = g_Hst + key_s[r1] * 64;
                float inv0 = 1.0f / (sqrtf(sumsq_s[r0] * (1.0f / 12240.0f)) + 1e-8f);
                float inv1 = 1.0f / (sqrtf(sumsq_s[r1] * (1.0f / 12240.0f)) + 1e-8f);
#pragma unroll
                for (int nt = 0; nt < 4; nt++) {
                    int col = cb + nt * 8;
                    Rbuf[r0 * RS + col]     = fmaxf((acc[mt][nt][0] + Rbuf[r0 * RS + col]     + H0[col])     * inv0, 0.f);
                    Rbuf[r0 * RS + col + 1] = fmaxf((acc[mt][nt][1] + Rbuf[r0 * RS + col + 1] + H0[col + 1]) * inv0, 0.f);
                    Rbuf[r1 * RS + col]     = fmaxf((acc[mt][nt][2] + Rbuf[r1 * RS + col]     + H1[col])     * inv1, 0.f);
                    Rbuf[r1 * RS + col + 1] = fmaxf((acc[mt][nt][3] + Rbuf[r1 * RS + col + 1] + H1[col + 1]) * inv1, 0.f);
                }
            }
        }
    }
    __syncthreads();

    // ---- final tiny layer + sigmoid ---------------------------------------
    if (tid < MPTS) {
        int gp = p0 + tid;
        float o0 = b_final[0], o1 = b_final[1], o2 = b_final[2], o3 = b_final[3];
#pragma unroll 8
        for (int i = 0; i < 64; i++) {
            float h = Rbuf[tid * RS + i];
            float4 wf = *reinterpret_cast<const float4*>(w_final + i * 4);
            o0 += h * wf.x; o1 += h * wf.y; o2 += h * wf.z; o3 += h * wf.w;
        }
#pragma unroll
        for (int c = 0; c < 3; c++) {
            float dv = d_dir[gp * 3 + c];
            float4 wf = *reinterpret_cast<const float4*>(w_final + (64 + c) * 4);
            o0 += dv * wf.x; o1 += dv * wf.y; o2 += dv * wf.z; o3 += dv * wf.w;
        }
        {
            float tv = d_t[gp];
            float4 wf = *reinterpret_cast<const float4*>(w_final + 67 * 4);
            o0 += tv * wf.x; o1 += tv * wf.y; o2 += tv * wf.z; o3 += tv * wf.w;
        }
        d_out[gp * 4 + 0] = 1.0f / (1.0f + expf(-o0));
        d_out[gp * 4 + 1] = 1.0f / (1.0f + expf(-o1));
        d_out[gp * 4 + 2] = 1.0f / (1.0f + expf(-o2));
        d_out[gp * 4 + 3] = 1.0f / (1.0f + expf(-o3));
    }
}

extern "C" void kernel_launch(void* const* d_in, const int* in_sizes, int n_in,
                              void* d_out, int out_size) {
    const float* pos       = (const float*)d_in[0];
    const float* dirv      = (const float*)d_in[1];
    const float* t         = (const float*)d_in[2];
    const float* table0    = (const float*)d_in[3];
    const float* table1    = (const float*)d_in[4];
    const float* table2    = (const float*)d_in[5];
    const float* table3    = (const float*)d_in[6];
    const float* st1       = (const float*)d_in[7];
    const float* st2       = (const float*)d_in[8];
    const float* tf3       = (const float*)d_in[9];
    const float* rms_scale = (const float*)d_in[10];
    const float* w_down    = (const float*)d_in[11];
    const float* w_final   = (const float*)d_in[12];
    const float* b_final   = (const float*)d_in[13];
    float* out = (float*)d_out;

    wf_precompute_kernel<<<(WF4_N + WST_N + NPTS + 255) / 256, 256>>>(w_down, rms_scale, t);
    st_precompute_kernel<<<NCOMBO, 256>>>(st1, st2, tf3);
    stlt_fused_kernel<<<8192 / MPTS, TPB>>>(
        pos, dirv, t, table0, table1, table2, table3,
        w_final, b_final, out);
}